// round 1
// baseline (speedup 1.0000x reference)
#include <cuda_runtime.h>
#include <cuda_bf16.h>

#define N_NODES_MAX 100000
#define IN_FEATS    128
#define HIDDEN      256

// Scratch: per-node projections u = Hs@W1a + b1, v = Hd@W1b  (fp32)
__device__ float g_u[(size_t)N_NODES_MAX * HIDDEN];
__device__ float g_v[(size_t)N_NODES_MAX * HIDDEN];

// ---------------------------------------------------------------------------
// Node GEMM: C[M, 256] = A[M, 128] @ B[128, 256] (+bias for the u half)
// Classic register-tiled SGEMM: BM=128, BN=128, BK=8, 8x8 per thread, 256 thr.
// blockIdx.z = 0 -> u (A=Hs, B=W1 rows 0..127, +b1)
// blockIdx.z = 1 -> v (A=Hd, B=W1 rows 128..255)
// ---------------------------------------------------------------------------
__global__ __launch_bounds__(256, 2)
void node_gemm_kernel(const float* __restrict__ Hs,
                      const float* __restrict__ Hd,
                      const float* __restrict__ W1,
                      const float* __restrict__ b1,
                      int M)
{
    constexpr int BM = 128, BN = 128, BK = 8;
    __shared__ float As[BK][BM];   // transposed A tile
    __shared__ float Bs[BK][BN];

    const bool is_u = (blockIdx.z == 0);
    const float* __restrict__ A = is_u ? Hs : Hd;
    const float* __restrict__ B = W1 + (is_u ? 0 : (size_t)IN_FEATS * HIDDEN);
    float* __restrict__ C = is_u ? g_u : g_v;

    const int bm = blockIdx.y * BM;
    const int bn = blockIdx.x * BN;
    const int tid = threadIdx.x;

    // global-load mapping
    const int aRow = tid >> 1;          // 0..127
    const int aCol = (tid & 1) * 4;     // 0 or 4
    const int bRow = tid >> 5;          // 0..7
    const int bCol = (tid & 31) * 4;    // 0..124

    // compute mapping: 16x16 thread grid of 8x8 micro-tiles
    const int tRow = (tid >> 4) * 8;
    const int tCol = (tid & 15) * 8;

    float acc[8][8] = {};

    for (int kt = 0; kt < IN_FEATS; kt += BK) {
        // load A tile (guard M edge), store transposed
        float4 a4 = make_float4(0.f, 0.f, 0.f, 0.f);
        if (bm + aRow < M)
            a4 = *reinterpret_cast<const float4*>(
                A + (size_t)(bm + aRow) * IN_FEATS + kt + aCol);
        As[aCol + 0][aRow] = a4.x;
        As[aCol + 1][aRow] = a4.y;
        As[aCol + 2][aRow] = a4.z;
        As[aCol + 3][aRow] = a4.w;

        // load B tile (W1 is [128 or 256, 256] row-major, always in-bounds)
        float4 b4 = *reinterpret_cast<const float4*>(
            B + (size_t)(kt + bRow) * HIDDEN + bn + bCol);
        *reinterpret_cast<float4*>(&Bs[bRow][bCol]) = b4;

        __syncthreads();

        #pragma unroll
        for (int k = 0; k < BK; k++) {
            float4 ra0 = *reinterpret_cast<const float4*>(&As[k][tRow]);
            float4 ra1 = *reinterpret_cast<const float4*>(&As[k][tRow + 4]);
            float4 rb0 = *reinterpret_cast<const float4*>(&Bs[k][tCol]);
            float4 rb1 = *reinterpret_cast<const float4*>(&Bs[k][tCol + 4]);
            float ra[8] = {ra0.x, ra0.y, ra0.z, ra0.w, ra1.x, ra1.y, ra1.z, ra1.w};
            float rb[8] = {rb0.x, rb0.y, rb0.z, rb0.w, rb1.x, rb1.y, rb1.z, rb1.w};
            #pragma unroll
            for (int i = 0; i < 8; i++)
                #pragma unroll
                for (int j = 0; j < 8; j++)
                    acc[i][j] = fmaf(ra[i], rb[j], acc[i][j]);
        }
        __syncthreads();
    }

    // epilogue: optional bias, vectorized store
    #pragma unroll
    for (int i = 0; i < 8; i++) {
        const int r = bm + tRow + i;
        if (r >= M) continue;
        #pragma unroll
        for (int j = 0; j < 8; j += 4) {
            float4 o;
            o.x = acc[i][j + 0];
            o.y = acc[i][j + 1];
            o.z = acc[i][j + 2];
            o.w = acc[i][j + 3];
            if (is_u) {
                const float4 bb = *reinterpret_cast<const float4*>(
                    b1 + bn + tCol + j);
                o.x += bb.x; o.y += bb.y; o.z += bb.z; o.w += bb.w;
            }
            *reinterpret_cast<float4*>(
                C + (size_t)r * HIDDEN + bn + tCol + j) = o;
        }
    }
}

// ---------------------------------------------------------------------------
// Edge pass: one warp per edge.
// score[e] = sum_j relu(u[src[e]][j] + v[dst[e]][j]) * W2[j] + b2
// Lane k owns hidden cols [4k..4k+3] and [128+4k..128+4k+3] (float4 loads).
// ---------------------------------------------------------------------------
__global__ __launch_bounds__(256)
void edge_score_kernel(const int* __restrict__ src,
                       const int* __restrict__ dst,
                       const float* __restrict__ W2,
                       const float* __restrict__ b2,
                       float* __restrict__ out,
                       int E)
{
    __shared__ float sW2[HIDDEN];
    const int tid = threadIdx.x;
    sW2[tid] = W2[tid];           // blockDim == HIDDEN == 256
    __syncthreads();

    const int lane = tid & 31;
    const int warp = tid >> 5;

    const float4 w2a = *reinterpret_cast<const float4*>(&sW2[lane * 4]);
    const float4 w2b = *reinterpret_cast<const float4*>(&sW2[128 + lane * 4]);
    const float bias = b2[0];

    int e = blockIdx.x * 8 + warp;
    if (e >= E) return;

    const int s = src[e];
    const int d = dst[e];
    const float4* __restrict__ up =
        reinterpret_cast<const float4*>(g_u + (size_t)s * HIDDEN);
    const float4* __restrict__ vp =
        reinterpret_cast<const float4*>(g_v + (size_t)d * HIDDEN);

    const float4 ua = up[lane];
    const float4 ub = up[32 + lane];
    const float4 va = vp[lane];
    const float4 vb = vp[32 + lane];

    float acc;
    acc  = fmaxf(ua.x + va.x, 0.f) * w2a.x;
    acc += fmaxf(ua.y + va.y, 0.f) * w2a.y;
    acc += fmaxf(ua.z + va.z, 0.f) * w2a.z;
    acc += fmaxf(ua.w + va.w, 0.f) * w2a.w;
    acc += fmaxf(ub.x + vb.x, 0.f) * w2b.x;
    acc += fmaxf(ub.y + vb.y, 0.f) * w2b.y;
    acc += fmaxf(ub.z + vb.z, 0.f) * w2b.z;
    acc += fmaxf(ub.w + vb.w, 0.f) * w2b.w;

    #pragma unroll
    for (int o = 16; o > 0; o >>= 1)
        acc += __shfl_xor_sync(0xFFFFFFFFu, acc, o);

    if (lane == 0) out[e] = acc + bias;
}

// ---------------------------------------------------------------------------
// Launch: inputs in metadata order
//   0: h_src_nodes [N,128] f32   1: h_dst_nodes [N,128] f32
//   2: src [E] i32               3: dst [E] i32
//   4: W1 [256,256] f32          5: b1 [256] f32
//   6: W2 [256,1] f32            7: b2 [1] f32
// out: score [E] f32
// ---------------------------------------------------------------------------
extern "C" void kernel_launch(void* const* d_in, const int* in_sizes, int n_in,
                              void* d_out, int out_size)
{
    const float* Hs = (const float*)d_in[0];
    const float* Hd = (const float*)d_in[1];
    const int*   src = (const int*)d_in[2];
    const int*   dst = (const int*)d_in[3];
    const float* W1 = (const float*)d_in[4];
    const float* b1 = (const float*)d_in[5];
    const float* W2 = (const float*)d_in[6];
    const float* b2 = (const float*)d_in[7];
    float* out = (float*)d_out;

    const int M = in_sizes[0] / IN_FEATS;   // 100000
    const int E = in_sizes[2];              // 1000000

    dim3 gemm_grid(HIDDEN / 128, (M + 127) / 128, 2);
    node_gemm_kernel<<<gemm_grid, 256>>>(Hs, Hd, W1, b1, M);

    edge_score_kernel<<<(E + 7) / 8, 256>>>(src, dst, W2, b2, out, E);
}